// round 1
// baseline (speedup 1.0000x reference)
#include <cuda_runtime.h>
#include <math.h>

// ---------------------------------------------------------------------------
// MultiHeadAttention: B=8, L=1024, D_MODEL=1024, H=16, Dk=64
// out = softmax((q Wq)(k Wk)^T / sqrt(Dk)) (v Wv) Wfc
// d_out = [ out (8*1024*1024 f32) | attn_flat ((16*8)*1024*1024 f32) ]
// attn_flat index: ((h*8 + b)*1024 + qi)*1024 + ki
// ---------------------------------------------------------------------------

#define BATCH 8
#define SEQ   1024
#define DMODEL 1024
#define NHEAD 16
#define DK    64
#define MROWS (BATCH * SEQ)          // 8192
#define OUT_ELEMS (MROWS * DMODEL)   // 8388608

// Scratch (static device memory, no allocations)
__device__ float g_qh[MROWS * DMODEL];
__device__ float g_kh[MROWS * DMODEL];
__device__ float g_vh[MROWS * DMODEL];
__device__ float g_ctx[MROWS * DMODEL];

// ---------------------------------------------------------------------------
// 128x128x8 fp32 SGEMM: C[M,N] = A[M,K] @ B[K,N] + bias[N]
// M,N multiples of 128; K multiple of 8. 256 threads, 8x8 per thread.
// ---------------------------------------------------------------------------
__global__ __launch_bounds__(256) void sgemm_128x128(
    const float* __restrict__ A, const float* __restrict__ B,
    const float* __restrict__ bias, float* __restrict__ C,
    int M, int N, int K)
{
    __shared__ float As[8][128];
    __shared__ float Bs[8][128];

    const int tid = threadIdx.x;
    const int tx = tid & 15;        // 0..15
    const int ty = tid >> 4;        // 0..15
    const int rowBlock = blockIdx.y * 128;
    const int colBlock = blockIdx.x * 128;

    // A tile load: 128x8 floats, 4 per thread (float4 along K)
    const int ar = tid >> 1;        // 0..127
    const int ac = (tid & 1) * 4;   // 0 or 4
    // B tile load: 8x128 floats, 4 per thread (float4 along N)
    const int br = tid >> 5;        // 0..7
    const int bc = (tid & 31) * 4;  // 0..124

    float acc[8][8];
    #pragma unroll
    for (int i = 0; i < 8; i++)
        #pragma unroll
        for (int j = 0; j < 8; j++) acc[i][j] = 0.f;

    for (int k0 = 0; k0 < K; k0 += 8) {
        float4 av = *(const float4*)(A + (long long)(rowBlock + ar) * K + k0 + ac);
        As[ac + 0][ar] = av.x;
        As[ac + 1][ar] = av.y;
        As[ac + 2][ar] = av.z;
        As[ac + 3][ar] = av.w;
        float4 bv = *(const float4*)(B + (long long)(k0 + br) * N + colBlock + bc);
        *(float4*)&Bs[br][bc] = bv;
        __syncthreads();

        #pragma unroll
        for (int k = 0; k < 8; k++) {
            float a[8], b[8];
            #pragma unroll
            for (int i = 0; i < 4; i++) {
                ((float4*)a)[0] = *(const float4*)&As[k][ty * 8];
                ((float4*)a)[1] = *(const float4*)&As[k][ty * 8 + 4];
                ((float4*)b)[0] = *(const float4*)&Bs[k][tx * 8];
                ((float4*)b)[1] = *(const float4*)&Bs[k][tx * 8 + 4];
                break;
            }
            #pragma unroll
            for (int i = 0; i < 8; i++)
                #pragma unroll
                for (int j = 0; j < 8; j++)
                    acc[i][j] = fmaf(a[i], b[j], acc[i][j]);
        }
        __syncthreads();
    }

    #pragma unroll
    for (int i = 0; i < 8; i++) {
        const int row = rowBlock + ty * 8 + i;
        #pragma unroll
        for (int j = 0; j < 8; j += 4) {
            const int col = colBlock + tx * 8 + j;
            float4 o;
            o.x = acc[i][j + 0] + bias[col + 0];
            o.y = acc[i][j + 1] + bias[col + 1];
            o.z = acc[i][j + 2] + bias[col + 2];
            o.w = acc[i][j + 3] + bias[col + 3];
            *(float4*)(C + (long long)row * N + col) = o;
        }
    }
}

// ---------------------------------------------------------------------------
// Scores: attn[(h*8+b), qi, ki] = 0.125 * sum_d qh[b,qi,h,d]*kh[b,ki,h,d]
// Per (b,h): GEMM [1024 x 64] x [64 x 1024]. 64x64 tiles, K=64 in BK=16 steps.
// blockIdx = (ki_tile 16, qi_tile 16, bh 128) where bh = h*8 + b.
// ---------------------------------------------------------------------------
__global__ __launch_bounds__(256) void scores_kernel(
    const float* __restrict__ qh, const float* __restrict__ kh,
    float* __restrict__ attn)
{
    __shared__ float As[16][64];   // [d][qi]
    __shared__ float Bs[16][64];   // [d][ki]

    const int tid = threadIdx.x;
    const int tx = tid & 15;
    const int ty = tid >> 4;
    const int kiBlock = blockIdx.x * 64;
    const int qiBlock = blockIdx.y * 64;
    const int bh = blockIdx.z;       // h*8 + b
    const int b  = bh & 7;
    const int h  = bh >> 3;

    const long long qbase = (long long)b * SEQ * DMODEL + h * DK;
    const long long kbase = qbase;   // same layout for kh
    const long long obase = (long long)bh * SEQ * SEQ;

    const int lrow = tid >> 2;          // 0..63
    const int lcol = (tid & 3) * 4;     // 0,4,8,12

    float acc[4][4];
    #pragma unroll
    for (int i = 0; i < 4; i++)
        #pragma unroll
        for (int j = 0; j < 4; j++) acc[i][j] = 0.f;

    for (int k0 = 0; k0 < DK; k0 += 16) {
        float4 av = *(const float4*)(qh + qbase + (long long)(qiBlock + lrow) * DMODEL + k0 + lcol);
        As[lcol + 0][lrow] = av.x;
        As[lcol + 1][lrow] = av.y;
        As[lcol + 2][lrow] = av.z;
        As[lcol + 3][lrow] = av.w;
        float4 bv = *(const float4*)(kh + kbase + (long long)(kiBlock + lrow) * DMODEL + k0 + lcol);
        Bs[lcol + 0][lrow] = bv.x;
        Bs[lcol + 1][lrow] = bv.y;
        Bs[lcol + 2][lrow] = bv.z;
        Bs[lcol + 3][lrow] = bv.w;
        __syncthreads();

        #pragma unroll
        for (int k = 0; k < 16; k++) {
            float a[4], bb[4];
            *(float4*)a  = *(const float4*)&As[k][ty * 4];
            *(float4*)bb = *(const float4*)&Bs[k][tx * 4];
            #pragma unroll
            for (int i = 0; i < 4; i++)
                #pragma unroll
                for (int j = 0; j < 4; j++)
                    acc[i][j] = fmaf(a[i], bb[j], acc[i][j]);
        }
        __syncthreads();
    }

    const float scale = 0.125f;   // 1/sqrt(64)
    #pragma unroll
    for (int i = 0; i < 4; i++) {
        const int qi = qiBlock + ty * 4 + i;
        float4 o;
        o.x = acc[i][0] * scale;
        o.y = acc[i][1] * scale;
        o.z = acc[i][2] * scale;
        o.w = acc[i][3] * scale;
        *(float4*)(attn + obase + (long long)qi * SEQ + kiBlock + tx * 4) = o;
    }
}

// ---------------------------------------------------------------------------
// Row softmax in place: 131072 rows of 1024. 256 threads/block, float4 each.
// ---------------------------------------------------------------------------
__global__ __launch_bounds__(256) void softmax_kernel(float* __restrict__ attn)
{
    __shared__ float warpred[8];
    __shared__ float s_bcast;

    const long long row = blockIdx.x;
    float* p = attn + row * SEQ;
    const int tid = threadIdx.x;
    const int lane = tid & 31;
    const int wid = tid >> 5;

    float4 v = *(float4*)(p + tid * 4);
    float m = fmaxf(fmaxf(v.x, v.y), fmaxf(v.z, v.w));
    #pragma unroll
    for (int o = 16; o; o >>= 1) m = fmaxf(m, __shfl_xor_sync(0xffffffffu, m, o));
    if (lane == 0) warpred[wid] = m;
    __syncthreads();
    if (tid == 0) {
        float mm = warpred[0];
        #pragma unroll
        for (int i = 1; i < 8; i++) mm = fmaxf(mm, warpred[i]);
        s_bcast = mm;
    }
    __syncthreads();
    m = s_bcast;

    v.x = expf(v.x - m);
    v.y = expf(v.y - m);
    v.z = expf(v.z - m);
    v.w = expf(v.w - m);
    float s = v.x + v.y + v.z + v.w;
    #pragma unroll
    for (int o = 16; o; o >>= 1) s += __shfl_xor_sync(0xffffffffu, s, o);
    if (lane == 0) warpred[wid] = s;
    __syncthreads();
    if (tid == 0) {
        float ss = warpred[0];
        #pragma unroll
        for (int i = 1; i < 8; i++) ss += warpred[i];
        s_bcast = 1.0f / ss;
    }
    __syncthreads();
    const float inv = s_bcast;

    v.x *= inv; v.y *= inv; v.z *= inv; v.w *= inv;
    *(float4*)(p + tid * 4) = v;
}

// ---------------------------------------------------------------------------
// attn @ V: ctx[b,qi,h,d] = sum_ki attn[(h*8+b),qi,ki] * vh[b,ki,h,d]
// Per (b,h): GEMM [1024 x 1024] x [1024 x 64]. 64-row tiles, BN=64 (full Dk).
// blockIdx = (qi_tile 16, bh 128).
// ---------------------------------------------------------------------------
__global__ __launch_bounds__(256) void attnv_kernel(
    const float* __restrict__ attn, const float* __restrict__ vh,
    float* __restrict__ ctx)
{
    __shared__ float As[16][64];   // [ki][qi]
    __shared__ float Bs[16][64];   // [ki][d]

    const int tid = threadIdx.x;
    const int tx = tid & 15;
    const int ty = tid >> 4;
    const int qiBlock = blockIdx.x * 64;
    const int bh = blockIdx.y;     // h*8 + b
    const int b  = bh & 7;
    const int h  = bh >> 3;

    const long long abase = (long long)bh * SEQ * SEQ;
    const long long vbase = (long long)b * SEQ * DMODEL + h * DK;
    const long long cbase = (long long)b * SEQ * DMODEL + h * DK;

    const int arow = tid >> 2;           // 0..63 (qi within tile)
    const int acol = (tid & 3) * 4;      // 0..12 (ki within BK)
    const int brow = tid >> 4;           // 0..15 (ki within BK)
    const int bcol = (tid & 15) * 4;     // 0..60 (d)

    float acc[4][4];
    #pragma unroll
    for (int i = 0; i < 4; i++)
        #pragma unroll
        for (int j = 0; j < 4; j++) acc[i][j] = 0.f;

    for (int k0 = 0; k0 < SEQ; k0 += 16) {
        float4 av = *(const float4*)(attn + abase + (long long)(qiBlock + arow) * SEQ + k0 + acol);
        As[acol + 0][arow] = av.x;
        As[acol + 1][arow] = av.y;
        As[acol + 2][arow] = av.z;
        As[acol + 3][arow] = av.w;
        float4 bv = *(const float4*)(vh + vbase + (long long)(k0 + brow) * DMODEL + bcol);
        *(float4*)&Bs[brow][bcol] = bv;
        __syncthreads();

        #pragma unroll
        for (int k = 0; k < 16; k++) {
            float a[4], bb[4];
            *(float4*)a  = *(const float4*)&As[k][ty * 4];
            *(float4*)bb = *(const float4*)&Bs[k][tx * 4];
            #pragma unroll
            for (int i = 0; i < 4; i++)
                #pragma unroll
                for (int j = 0; j < 4; j++)
                    acc[i][j] = fmaf(a[i], bb[j], acc[i][j]);
        }
        __syncthreads();
    }

    #pragma unroll
    for (int i = 0; i < 4; i++) {
        const int qi = qiBlock + ty * 4 + i;
        float4 o;
        o.x = acc[i][0]; o.y = acc[i][1]; o.z = acc[i][2]; o.w = acc[i][3];
        *(float4*)(ctx + cbase + (long long)qi * DMODEL + tx * 4) = o;
    }
}

// ---------------------------------------------------------------------------
// Launcher
// ---------------------------------------------------------------------------
extern "C" void kernel_launch(void* const* d_in, const int* in_sizes, int n_in,
                              void* d_out, int out_size)
{
    (void)in_sizes; (void)n_in; (void)out_size;

    const float* q   = (const float*)d_in[0];
    const float* k   = (const float*)d_in[1];
    const float* v   = (const float*)d_in[2];
    const float* Wq  = (const float*)d_in[3];
    const float* bq  = (const float*)d_in[4];
    const float* Wk  = (const float*)d_in[5];
    const float* bk  = (const float*)d_in[6];
    const float* Wv  = (const float*)d_in[7];
    const float* bv  = (const float*)d_in[8];
    const float* Wfc = (const float*)d_in[9];
    const float* bfc = (const float*)d_in[10];

    float* out  = (float*)d_out;
    float* attn = out + OUT_ELEMS;   // attn_flat region

    float *qh, *kh, *vh, *ctx;
    cudaGetSymbolAddress((void**)&qh,  g_qh);
    cudaGetSymbolAddress((void**)&kh,  g_kh);
    cudaGetSymbolAddress((void**)&vh,  g_vh);
    cudaGetSymbolAddress((void**)&ctx, g_ctx);

    dim3 gProj(DMODEL / 128, MROWS / 128);   // (8, 64)
    sgemm_128x128<<<gProj, 256>>>(q, Wq, bq, qh, MROWS, DMODEL, DMODEL);
    sgemm_128x128<<<gProj, 256>>>(k, Wk, bk, kh, MROWS, DMODEL, DMODEL);
    sgemm_128x128<<<gProj, 256>>>(v, Wv, bv, vh, MROWS, DMODEL, DMODEL);

    dim3 gScores(SEQ / 64, SEQ / 64, BATCH * NHEAD);   // (16,16,128)
    scores_kernel<<<gScores, 256>>>(qh, kh, attn);

    softmax_kernel<<<BATCH * NHEAD * SEQ, 256>>>(attn);  // 131072 rows

    dim3 gAV(SEQ / 64, BATCH * NHEAD);   // (16,128)
    attnv_kernel<<<gAV, 256>>>(attn, vh, ctx);

    sgemm_128x128<<<gProj, 256>>>(ctx, Wfc, bfc, out, MROWS, DMODEL, DMODEL);
}

// round 2
// speedup vs baseline: 1.3896x; 1.3896x over previous
#include <cuda_runtime.h>
#include <cuda_bf16.h>
#include <math.h>
#include <stdint.h>

// ---------------------------------------------------------------------------
// MultiHeadAttention: B=8, L=1024, D_MODEL=1024, H=16, Dk=64
// All GEMMs on tensor cores: mma.sync.m16n8k16 bf16 with bf16x3 split
// (a = hi + lo; C = hi*hi + lo*hi + hi*lo) -> ~1e-5 relative accuracy.
// d_out = [ out (8*1024*1024 f32) | attn_flat ((16*8)*1024*1024 f32) ]
// ---------------------------------------------------------------------------

#define BATCH 8
#define SEQ   1024
#define DMODEL 1024
#define NHEAD 16
#define DK    64
#define MROWS (BATCH * SEQ)          // 8192
#define OUT_ELEMS (MROWS * DMODEL)   // 8388608

#define BKP  40    // 32 + 8 pad (bf16 elems) for [*][BK] tiles
#define BNP  136   // 128 + 8 pad for [k][n] tiles (proj B)
#define BNP2 72    // 64 + 8 pad for [k][n] tiles (attnv B)

// Scratch (static device memory, no allocations)
__device__ float g_qh[MROWS * DMODEL];
__device__ float g_kh[MROWS * DMODEL];
__device__ float g_vh[MROWS * DMODEL];
__device__ float g_ctx[MROWS * DMODEL];

// ---------------------------------------------------------------------------
// PTX helpers
// ---------------------------------------------------------------------------
__device__ __forceinline__ uint32_t smem_u32(const void* p) {
    return (uint32_t)__cvta_generic_to_shared(p);
}

#define LDMX4(r0,r1,r2,r3,addr) \
    asm volatile("ldmatrix.sync.aligned.m8n8.x4.shared.b16 {%0,%1,%2,%3}, [%4];" \
        : "=r"(r0), "=r"(r1), "=r"(r2), "=r"(r3) : "r"(addr))

#define LDMX4T(r0,r1,r2,r3,addr) \
    asm volatile("ldmatrix.sync.aligned.m8n8.x4.trans.shared.b16 {%0,%1,%2,%3}, [%4];" \
        : "=r"(r0), "=r"(r1), "=r"(r2), "=r"(r3) : "r"(addr))

#define MMA16816(c, a, b) \
    asm volatile("mma.sync.aligned.m16n8k16.row.col.f32.bf16.bf16.f32 " \
        "{%0,%1,%2,%3}, {%4,%5,%6,%7}, {%8,%9}, {%0,%1,%2,%3};" \
        : "+f"((c)[0]), "+f"((c)[1]), "+f"((c)[2]), "+f"((c)[3]) \
        : "r"((a)[0]), "r"((a)[1]), "r"((a)[2]), "r"((a)[3]), \
          "r"((b)[0]), "r"((b)[1]))

__device__ __forceinline__ void split_store(float x, __nv_bfloat16* hi, __nv_bfloat16* lo) {
    __nv_bfloat16 h = __float2bfloat16(x);
    *hi = h;
    *lo = __float2bfloat16(x - __bfloat162float(h));
}

// ---------------------------------------------------------------------------
// Core K-tile compute: 2 m-subtiles x NSUB n-subtiles, BK=32 (2 x k16).
// A tiles: [128][BKP] bf16 (row-major M x K).
// B tiles: BTRANS ? [32][BSTRIDE] (k-major rows, ldmatrix.trans)
//                 : [BN][BSTRIDE] (n rows of k, plain ldmatrix).
// ---------------------------------------------------------------------------
template<bool BTRANS, int NSUB, int BSTRIDE>
__device__ __forceinline__ void mma_ktile(
    uint32_t sAhi, uint32_t sAlo, uint32_t sBhi, uint32_t sBlo,
    int wm, int wn, int lane, float (&acc)[2][NSUB][4])
{
    const int alr = (lane & 7) + ((lane >> 3) & 1) * 8;
    const int alc = (lane >> 4) * 8;

    #pragma unroll
    for (int kk = 0; kk < 32; kk += 16) {
        uint32_t ahi[2][4], alo[2][4];
        #pragma unroll
        for (int ms = 0; ms < 2; ms++) {
            uint32_t off = (uint32_t)((wm * 32 + ms * 16 + alr) * BKP + kk + alc) * 2;
            LDMX4(ahi[ms][0], ahi[ms][1], ahi[ms][2], ahi[ms][3], sAhi + off);
            LDMX4(alo[ms][0], alo[ms][1], alo[ms][2], alo[ms][3], sAlo + off);
        }

        uint32_t bhi[NSUB][2], blo[NSUB][2];
        #pragma unroll
        for (int np = 0; np < NSUB / 2; np++) {
            uint32_t r0, r1, r2, r3;
            if (BTRANS) {
                const int krow = (lane & 7) + ((lane >> 3) & 1) * 8;
                const int ncol = ((lane >> 4) & 1) * 8;
                uint32_t off = (uint32_t)((kk + krow) * BSTRIDE +
                                          wn * (NSUB * 8) + np * 16 + ncol) * 2;
                LDMX4T(r0, r1, r2, r3, sBhi + off);
                bhi[np*2][0] = r0; bhi[np*2][1] = r1;
                bhi[np*2+1][0] = r2; bhi[np*2+1][1] = r3;
                LDMX4T(r0, r1, r2, r3, sBlo + off);
                blo[np*2][0] = r0; blo[np*2][1] = r1;
                blo[np*2+1][0] = r2; blo[np*2+1][1] = r3;
            } else {
                const int nrow = (lane & 7) + ((lane >> 4) & 1) * 8;
                const int kc = ((lane >> 3) & 1) * 8;
                uint32_t off = (uint32_t)((wn * (NSUB * 8) + np * 16 + nrow) * BSTRIDE +
                                          kk + kc) * 2;
                LDMX4(r0, r1, r2, r3, sBhi + off);
                bhi[np*2][0] = r0; bhi[np*2][1] = r1;
                bhi[np*2+1][0] = r2; bhi[np*2+1][1] = r3;
                LDMX4(r0, r1, r2, r3, sBlo + off);
                blo[np*2][0] = r0; blo[np*2][1] = r1;
                blo[np*2+1][0] = r2; blo[np*2+1][1] = r3;
            }
        }

        #pragma unroll
        for (int ms = 0; ms < 2; ms++)
            #pragma unroll
            for (int ns = 0; ns < NSUB; ns++) {
                MMA16816(acc[ms][ns], ahi[ms], bhi[ns]);
                MMA16816(acc[ms][ns], alo[ms], bhi[ns]);
                MMA16816(acc[ms][ns], ahi[ms], blo[ns]);
            }
    }
}

// ---------------------------------------------------------------------------
// Projection / out-proj GEMM: C[M,N] = A[M,K] @ B[K,N] + bias.
// 128x128 block tile, BK=32, 512 threads (16 warps, 4x4, warp tile 32x32).
// ---------------------------------------------------------------------------
__global__ __launch_bounds__(512, 1) void proj_gemm(
    const float* __restrict__ A, const float* __restrict__ B,
    const float* __restrict__ bias, float* __restrict__ C,
    int M, int N, int K)
{
    __shared__ __nv_bfloat16 Ahi[128][BKP], Alo[128][BKP];
    __shared__ __nv_bfloat16 Bhi[32][BNP],  Blo[32][BNP];

    const int tid = threadIdx.x;
    const int warp = tid >> 5, lane = tid & 31;
    const int wm = warp & 3, wn = warp >> 2;
    const int rowBlock = blockIdx.y * 128;
    const int colBlock = blockIdx.x * 128;

    const uint32_t sAhi = smem_u32(&Ahi[0][0]);
    const uint32_t sAlo = smem_u32(&Alo[0][0]);
    const uint32_t sBhi = smem_u32(&Bhi[0][0]);
    const uint32_t sBlo = smem_u32(&Blo[0][0]);

    // A loader: 128x32 f32, 4 thr/row, 2 float4 each
    const int arow = tid >> 2;
    const int ac = (tid & 3) * 8;
    // B loader: 32x128 f32, 16 thr/row, 2 float4 each
    const int brow = tid >> 4;
    const int bc = (tid & 15) * 8;

    float4 pa[2], pb[2];
    #pragma unroll
    for (int i = 0; i < 2; i++) {
        pa[i] = *(const float4*)(A + (long long)(rowBlock + arow) * K + ac + i * 4);
        pb[i] = *(const float4*)(B + (long long)brow * N + colBlock + bc + i * 4);
    }

    float acc[2][4][4];
    #pragma unroll
    for (int i = 0; i < 2; i++)
        #pragma unroll
        for (int j = 0; j < 4; j++)
            #pragma unroll
            for (int l = 0; l < 4; l++) acc[i][j][l] = 0.f;

    for (int k0 = 0; k0 < K; k0 += 32) {
        #pragma unroll
        for (int i = 0; i < 2; i++) {
            const float* v = (const float*)&pa[i];
            #pragma unroll
            for (int j = 0; j < 4; j++)
                split_store(v[j], &Ahi[arow][ac + i*4 + j], &Alo[arow][ac + i*4 + j]);
            const float* w = (const float*)&pb[i];
            #pragma unroll
            for (int j = 0; j < 4; j++)
                split_store(w[j], &Bhi[brow][bc + i*4 + j], &Blo[brow][bc + i*4 + j]);
        }
        __syncthreads();

        if (k0 + 32 < K) {
            #pragma unroll
            for (int i = 0; i < 2; i++) {
                pa[i] = *(const float4*)(A + (long long)(rowBlock + arow) * K + k0 + 32 + ac + i * 4);
                pb[i] = *(const float4*)(B + (long long)(k0 + 32 + brow) * N + colBlock + bc + i * 4);
            }
        }

        mma_ktile<true, 4, BNP>(sAhi, sAlo, sBhi, sBlo, wm, wn, lane, acc);
        __syncthreads();
    }

    const int gid = lane >> 2, tig = lane & 3;
    #pragma unroll
    for (int ms = 0; ms < 2; ms++)
        #pragma unroll
        for (int ns = 0; ns < 4; ns++) {
            const int row = rowBlock + wm * 32 + ms * 16 + gid;
            const int col = colBlock + wn * 32 + ns * 8 + tig * 2;
            float2 bz = *(const float2*)(bias + col);
            float* a = acc[ms][ns];
            *(float2*)(C + (long long)row * N + col) =
                make_float2(a[0] + bz.x, a[1] + bz.y);
            *(float2*)(C + (long long)(row + 8) * N + col) =
                make_float2(a[2] + bz.x, a[3] + bz.y);
        }
}

// ---------------------------------------------------------------------------
// Scores: attn[(h*8+b), qi, ki] = 0.125 * sum_d qh[b,qi,h,d]*kh[b,ki,h,d]
// Per bh: [1024 x 64] x [64 x 1024]^T. 128x128 tiles, K=64 (2 k-tiles).
// B operand = kh rows (already col-major for the mma) -> plain ldmatrix.
// ---------------------------------------------------------------------------
__global__ __launch_bounds__(512, 1) void scores_mma(
    const float* __restrict__ qh, const float* __restrict__ kh,
    float* __restrict__ attn)
{
    __shared__ __nv_bfloat16 Ahi[128][BKP], Alo[128][BKP];
    __shared__ __nv_bfloat16 Bhi[128][BKP], Blo[128][BKP];

    const int tid = threadIdx.x;
    const int warp = tid >> 5, lane = tid & 31;
    const int wm = warp & 3, wn = warp >> 2;
    const int kiBlock = blockIdx.x * 128;
    const int qiBlock = blockIdx.y * 128;
    const int bh = blockIdx.z;      // h*8 + b
    const int b = bh & 7, h = bh >> 3;

    const long long qbase = (long long)b * SEQ * DMODEL + h * DK;
    const long long obase = (long long)bh * SEQ * SEQ;

    const uint32_t sAhi = smem_u32(&Ahi[0][0]);
    const uint32_t sAlo = smem_u32(&Alo[0][0]);
    const uint32_t sBhi = smem_u32(&Bhi[0][0]);
    const uint32_t sBlo = smem_u32(&Blo[0][0]);

    const int arow = tid >> 2;
    const int ac = (tid & 3) * 8;

    float acc[2][4][4];
    #pragma unroll
    for (int i = 0; i < 2; i++)
        #pragma unroll
        for (int j = 0; j < 4; j++)
            #pragma unroll
            for (int l = 0; l < 4; l++) acc[i][j][l] = 0.f;

    float4 pa[2], pb[2];
    #pragma unroll
    for (int i = 0; i < 2; i++) {
        pa[i] = *(const float4*)(qh + qbase + (long long)(qiBlock + arow) * DMODEL + ac + i * 4);
        pb[i] = *(const float4*)(kh + qbase + (long long)(kiBlock + arow) * DMODEL + ac + i * 4);
    }

    for (int k0 = 0; k0 < DK; k0 += 32) {
        #pragma unroll
        for (int i = 0; i < 2; i++) {
            const float* v = (const float*)&pa[i];
            #pragma unroll
            for (int j = 0; j < 4; j++)
                split_store(v[j], &Ahi[arow][ac + i*4 + j], &Alo[arow][ac + i*4 + j]);
            const float* w = (const float*)&pb[i];
            #pragma unroll
            for (int j = 0; j < 4; j++)
                split_store(w[j], &Bhi[arow][ac + i*4 + j], &Blo[arow][ac + i*4 + j]);
        }
        __syncthreads();

        if (k0 + 32 < DK) {
            #pragma unroll
            for (int i = 0; i < 2; i++) {
                pa[i] = *(const float4*)(qh + qbase + (long long)(qiBlock + arow) * DMODEL + k0 + 32 + ac + i * 4);
                pb[i] = *(const float4*)(kh + qbase + (long long)(kiBlock + arow) * DMODEL + k0 + 32 + ac + i * 4);
            }
        }

        mma_ktile<false, 4, BKP>(sAhi, sAlo, sBhi, sBlo, wm, wn, lane, acc);
        __syncthreads();
    }

    const int gid = lane >> 2, tig = lane & 3;
    const float scale = 0.125f;
    #pragma unroll
    for (int ms = 0; ms < 2; ms++)
        #pragma unroll
        for (int ns = 0; ns < 4; ns++) {
            const int row = qiBlock + wm * 32 + ms * 16 + gid;
            const int col = kiBlock + wn * 32 + ns * 8 + tig * 2;
            float* a = acc[ms][ns];
            *(float2*)(attn + obase + (long long)row * SEQ + col) =
                make_float2(a[0] * scale, a[1] * scale);
            *(float2*)(attn + obase + (long long)(row + 8) * SEQ + col) =
                make_float2(a[2] * scale, a[3] * scale);
        }
}

// ---------------------------------------------------------------------------
// Row softmax in place: 131072 rows of 1024.
// ---------------------------------------------------------------------------
__global__ __launch_bounds__(256) void softmax_kernel(float* __restrict__ attn)
{
    __shared__ float warpred[8];
    __shared__ float s_bcast;

    const long long row = blockIdx.x;
    float* p = attn + row * SEQ;
    const int tid = threadIdx.x;
    const int lane = tid & 31;
    const int wid = tid >> 5;

    float4 v = *(float4*)(p + tid * 4);
    float m = fmaxf(fmaxf(v.x, v.y), fmaxf(v.z, v.w));
    #pragma unroll
    for (int o = 16; o; o >>= 1) m = fmaxf(m, __shfl_xor_sync(0xffffffffu, m, o));
    if (lane == 0) warpred[wid] = m;
    __syncthreads();
    if (tid == 0) {
        float mm = warpred[0];
        #pragma unroll
        for (int i = 1; i < 8; i++) mm = fmaxf(mm, warpred[i]);
        s_bcast = mm;
    }
    __syncthreads();
    m = s_bcast;

    v.x = expf(v.x - m);
    v.y = expf(v.y - m);
    v.z = expf(v.z - m);
    v.w = expf(v.w - m);
    float s = v.x + v.y + v.z + v.w;
    #pragma unroll
    for (int o = 16; o; o >>= 1) s += __shfl_xor_sync(0xffffffffu, s, o);
    if (lane == 0) warpred[wid] = s;
    __syncthreads();
    if (tid == 0) {
        float ss = warpred[0];
        #pragma unroll
        for (int i = 1; i < 8; i++) ss += warpred[i];
        s_bcast = 1.0f / ss;
    }
    __syncthreads();
    const float inv = s_bcast;

    v.x *= inv; v.y *= inv; v.z *= inv; v.w *= inv;
    *(float4*)(p + tid * 4) = v;
}

// ---------------------------------------------------------------------------
// attn @ V: ctx[b,qi,h,d] = sum_ki attn[(h*8+b),qi,ki] * vh[b,ki,h,d]
// Per bh: [1024 x 1024] x [1024 x 64]. 128x64 tiles, BK=32, K=1024.
// 16 warps (4m x 4n), warp tile 32x16 (NSUB=2). B row-major -> trans.
// ---------------------------------------------------------------------------
__global__ __launch_bounds__(512, 1) void attnv_mma(
    const float* __restrict__ attn, const float* __restrict__ vh,
    float* __restrict__ ctx)
{
    __shared__ __nv_bfloat16 Ahi[128][BKP], Alo[128][BKP];
    __shared__ __nv_bfloat16 Bhi[32][BNP2], Blo[32][BNP2];

    const int tid = threadIdx.x;
    const int warp = tid >> 5, lane = tid & 31;
    const int wm = warp & 3, wn = warp >> 2;
    const int qiBlock = blockIdx.x * 128;
    const int bh = blockIdx.y;
    const int b = bh & 7, h = bh >> 3;

    const long long abase = (long long)bh * SEQ * SEQ;
    const long long vbase = (long long)b * SEQ * DMODEL + h * DK;

    const uint32_t sAhi = smem_u32(&Ahi[0][0]);
    const uint32_t sAlo = smem_u32(&Alo[0][0]);
    const uint32_t sBhi = smem_u32(&Bhi[0][0]);
    const uint32_t sBlo = smem_u32(&Blo[0][0]);

    const int arow = tid >> 2;
    const int ac = (tid & 3) * 8;
    const int brow = tid >> 4;       // 0..31
    const int bc = (tid & 15) * 4;   // 0..60

    float acc[2][2][4];
    #pragma unroll
    for (int i = 0; i < 2; i++)
        #pragma unroll
        for (int j = 0; j < 2; j++)
            #pragma unroll
            for (int l = 0; l < 4; l++) acc[i][j][l] = 0.f;

    float4 pa[2], pb;
    #pragma unroll
    for (int i = 0; i < 2; i++)
        pa[i] = *(const float4*)(attn + abase + (long long)(qiBlock + arow) * SEQ + ac + i * 4);
    pb = *(const float4*)(vh + vbase + (long long)brow * DMODEL + bc);

    for (int k0 = 0; k0 < SEQ; k0 += 32) {
        #pragma unroll
        for (int i = 0; i < 2; i++) {
            const float* v = (const float*)&pa[i];
            #pragma unroll
            for (int j = 0; j < 4; j++)
                split_store(v[j], &Ahi[arow][ac + i*4 + j], &Alo[arow][ac + i*4 + j]);
        }
        {
            const float* w = (const float*)&pb;
            #pragma unroll
            for (int j = 0; j < 4; j++)
                split_store(w[j], &Bhi[brow][bc + j], &Blo[brow][bc + j]);
        }
        __syncthreads();

        if (k0 + 32 < SEQ) {
            #pragma unroll
            for (int i = 0; i < 2; i++)
                pa[i] = *(const float4*)(attn + abase + (long long)(qiBlock + arow) * SEQ + k0 + 32 + ac + i * 4);
            pb = *(const float4*)(vh + vbase + (long long)(k0 + 32 + brow) * DMODEL + bc);
        }

        mma_ktile<true, 2, BNP2>(sAhi, sAlo, sBhi, sBlo, wm, wn, lane, acc);
        __syncthreads();
    }

    const int gid = lane >> 2, tig = lane & 3;
    #pragma unroll
    for (int ms = 0; ms < 2; ms++)
        #pragma unroll
        for (int ns = 0; ns < 2; ns++) {
            const int row = qiBlock + wm * 32 + ms * 16 + gid;
            const int col = wn * 16 + ns * 8 + tig * 2;
            float* a = acc[ms][ns];
            *(float2*)(ctx + vbase + (long long)row * DMODEL + col) =
                make_float2(a[0], a[1]);
            *(float2*)(ctx + vbase + (long long)(row + 8) * DMODEL + col) =
                make_float2(a[2], a[3]);
        }
}

// ---------------------------------------------------------------------------
// Launcher
// ---------------------------------------------------------------------------
extern "C" void kernel_launch(void* const* d_in, const int* in_sizes, int n_in,
                              void* d_out, int out_size)
{
    (void)in_sizes; (void)n_in; (void)out_size;

    const float* q   = (const float*)d_in[0];
    const float* k   = (const float*)d_in[1];
    const float* v   = (const float*)d_in[2];
    const float* Wq  = (const float*)d_in[3];
    const float* bq  = (const float*)d_in[4];
    const float* Wk  = (const float*)d_in[5];
    const float* bk  = (const float*)d_in[6];
    const float* Wv  = (const float*)d_in[7];
    const float* bv  = (const float*)d_in[8];
    const float* Wfc = (const float*)d_in[9];
    const float* bfc = (const float*)d_in[10];

    float* out  = (float*)d_out;
    float* attn = out + OUT_ELEMS;

    float *qh, *kh, *vh, *ctx;
    cudaGetSymbolAddress((void**)&qh,  g_qh);
    cudaGetSymbolAddress((void**)&kh,  g_kh);
    cudaGetSymbolAddress((void**)&vh,  g_vh);
    cudaGetSymbolAddress((void**)&ctx, g_ctx);

    dim3 gProj(DMODEL / 128, MROWS / 128);           // (8, 64)
    proj_gemm<<<gProj, 512>>>(q, Wq, bq, qh, MROWS, DMODEL, DMODEL);
    proj_gemm<<<gProj, 512>>>(k, Wk, bk, kh, MROWS, DMODEL, DMODEL);
    proj_gemm<<<gProj, 512>>>(v, Wv, bv, vh, MROWS, DMODEL, DMODEL);

    dim3 gScores(SEQ / 128, SEQ / 128, BATCH * NHEAD);  // (8,8,128)
    scores_mma<<<gScores, 512>>>(qh, kh, attn);

    softmax_kernel<<<BATCH * NHEAD * SEQ, 256>>>(attn);

    dim3 gAV(SEQ / 128, BATCH * NHEAD);              // (8,128)
    attnv_mma<<<gAV, 512>>>(attn, vh, ctx);

    proj_gemm<<<gProj, 512>>>(ctx, Wfc, bfc, out, MROWS, DMODEL, DMODEL);
}